// round 9
// baseline (speedup 1.0000x reference)
#include <cuda_runtime.h>

#define GDIM 7
#define GG 49
#define NWARPS 4             // 128-thread blocks
#define GRID_BLOCKS (148 * 16)

__device__ double   g_acc   = 0.0;
__device__ unsigned g_count = 0u;

struct SampleStream {
    float p0, p1;
    float qa0, qb0, qc0, qa1, qb1, qc1;
    float c0, c1;
    int   y;
};

__device__ __forceinline__ SampleStream
load_stream(const float* __restrict__ bbox, const float* __restrict__ bboxp,
            const float* __restrict__ clsp, const int* __restrict__ cls32,
            int b, int l, bool hi)
{
    SampleStream s;
    const float* bb = bbox  + (size_t)b * (5 * GG);
    const float* bp = bboxp + (size_t)b * (15 * GG);
    s.p0  = bb[l];
    s.p1  = hi ? bb[l + 32] : 0.0f;
    s.qa0 = bp[l];          s.qa1 = hi ? bp[l + 32]         : 0.5f;
    s.qb0 = bp[5*GG + l];   s.qb1 = hi ? bp[5*GG + l + 32]  : 0.5f;
    s.qc0 = bp[10*GG + l];  s.qc1 = hi ? bp[10*GG + l + 32] : 0.5f;
    s.c0 = 0.f; s.c1 = 0.f; s.y = 1;
    if (l == 0) {
        float2 cc = *(const float2*)(clsp + 2 * (size_t)b);
        s.c0 = cc.x; s.c1 = cc.y;
        s.y  = cls32[2 * b];
    }
    return s;
}

__global__ void __launch_bounds__(32 * NWARPS, 12)
loss_fused_kernel(const float* __restrict__ bboxp,   // (N,15,7,7)
                  const float* __restrict__ clsp,    // (N,2)
                  const float* __restrict__ bbox,    // (N,5,7,7)
                  const int*   __restrict__ cls32,   // (N,) int64 as int32 pairs
                  float* __restrict__ out,
                  int N, int chunk)
{
    const unsigned FULL = 0xffffffffu;
    const int warp = threadIdx.x >> 5;
    const int l    = threadIdx.x & 31;
    const bool hi  = (l < GG - 32);                  // l < 17
    const float inv7  = 1.0f / 7.0f;
    const float invN  = 1.0f / (float)N;
    const float invN49 = invN * (1.0f / 49.0f);

    const int wid   = blockIdx.x * NWARPS + warp;
    int b           = wid * chunk;
    const int b_end = min(b + chunk, N);

    float tot = 0.0f;

    if (b < b_end) {
        SampleStream S = load_stream(bbox, bboxp, clsp, cls32, b, l, hi);

        while (true) {
            const float* bb = bbox  + (size_t)b * (5 * GG);
            const float* bp = bboxp + (size_t)b * (15 * GG);

            // ---- exact argmax on sample b ----
            const unsigned w0 = __float_as_uint(S.p0);
            const unsigned w1 = hi ? __float_as_uint(S.p1) : 0u;
            const unsigned vmax = __reduce_max_sync(FULL, w0 > w1 ? w0 : w1);
            const unsigned bal0 = __ballot_sync(FULL, w0 == vmax);
            const unsigned bal1 = __ballot_sync(FULL, w1 == vmax);
            const int m = bal0 ? (__ffs(bal0) - 1) : (32 + __ffs(bal1) - 1);
            const float jf  = (float)(m % GDIM);
            const float if_ = (float)(m / GDIM);

            // ---- issue dependent gather for b (16 useful lanes, 64B fetch) ----
            float g = 0.0f;
            if (l < 16) {
                const float* gptr = (l < 12)
                    ? bp + ((l >> 2) * 5 + (l & 3) + 1) * GG + m
                    : bb + (l - 11) * GG + m;
                asm volatile("ld.global.L2::64B.f32 %0, [%1];" : "=f"(g) : "l"(gptr));
            }

            // ---- prefetch next sample's streams (overlaps the gather) ----
            const int bn = b + 1;
            const bool more = (bn < b_end);
            SampleStream Snext;
            if (more) Snext = load_stream(bbox, bboxp, clsp, cls32, bn, l, hi);

            // ---- independent log work also overlaps the gather ----
            float P = (1.0f - S.qa0) * (1.0f - S.qb0) * (1.0f - S.qc0);
            if (hi) P *= (1.0f - S.qa1) * (1.0f - S.qb1) * (1.0f - S.qc1);
            float s = -__logf(P);

            // ---- consume gather: broadcast gt, anchors to lanes 0..2 ----
            const float gt1 = __shfl_sync(FULL, g, 12);
            const float gt2 = __shfl_sync(FULL, g, 13);
            const float gt3 = __shfl_sync(FULL, g, 14);
            const float gt4 = __shfl_sync(FULL, g, 15);
            const int al = 4 * min(l, 2);
            const float a1 = __shfl_sync(FULL, g, al + 0);
            const float a2 = __shfl_sync(FULL, g, al + 1);
            const float a3 = __shfl_sync(FULL, g, al + 2);
            const float a4 = __shfl_sync(FULL, g, al + 3);

            // ---- IoU on lanes 0..2; winner via packed REDUX ----
            const float tx  = (gt1 + jf)  * inv7;
            const float ty  = (gt2 + if_) * inv7;
            const float tx1 = tx - gt3 * 0.5f, tx2 = tx + gt3 * 0.5f;
            const float ty1 = ty - gt4 * 0.5f, ty2 = ty + gt4 * 0.5f;
            const float tarea = (tx2 - tx1) * (ty2 - ty1);

            const float ax  = (a1 + jf)  * inv7;
            const float ay  = (a2 + if_) * inv7;
            const float ax1 = ax - a3 * 0.5f, ax2 = ax + a3 * 0.5f;
            const float ay1 = ay - a4 * 0.5f, ay2 = ay + a4 * 0.5f;
            float iw = fmaxf(fminf(ax2, tx2) - fmaxf(ax1, tx1), 0.0f);
            float ih = fmaxf(fminf(ay2, ty2) - fmaxf(ay1, ty1), 0.0f);
            float inter = iw * ih;
            float uni   = (ax2 - ax1) * (ay2 - ay1) + tarea - inter;
            float iou   = __fdividef(inter, uni + 1e-9f);

            unsigned key = (l < 3) ? ((__float_as_uint(iou) & ~3u) | (3u - l)) : 0u;
            key = __reduce_max_sync(FULL, key);
            const int best = 3 - (int)(key & 3u);

            // ---- BCE correction for best anchor ----
            float qb0 = (best == 0) ? S.qa0 : (best == 1) ? S.qb0 : S.qc0;
            s -= S.p0 * (__logf(qb0) - __logf(1.0f - qb0));
            if (hi) {
                float qb1 = (best == 0) ? S.qa1 : (best == 1) ? S.qb1 : S.qc1;
                s -= S.p1 * (__logf(qb1) - __logf(1.0f - qb1));
            }

            float t = s * invN49;

            // ---- coord + size on the winning anchor's lane ----
            if (l == best) {
                float coord = -(gt1 * __logf(a1) + (1.0f - gt1) * __logf(1.0f - a1))
                            + -(gt2 * __logf(a2) + (1.0f - gt2) * __logf(1.0f - a2));
                float size_ = fabsf(__logf(a3) - __logf(gt3))
                            + fabsf(__logf(a4) - __logf(gt4));
                t += coord + size_;
            }
            // ---- CE on lane 0 ----
            if (l == 0) {
                float mx  = fmaxf(S.c0, S.c1);
                float lse = mx + __logf(__expf(S.c0 - mx) + __expf(S.c1 - mx));
                float sel = (S.y == 1) ? S.c0 : S.c1;
                t += (lse - sel) * invN;
            }
            tot += t;

            if (!more) break;
            S = Snext;
            b = bn;
        }
    }

    // ---- warp reduce ----
    #pragma unroll
    for (int off = 16; off; off >>= 1)
        tot += __shfl_xor_sync(FULL, tot, off);

    // ---- block reduce -> one double atomic per block ----
    __shared__ float wsum[NWARPS];
    if (l == 0) wsum[warp] = tot;
    __syncthreads();
    if (threadIdx.x == 0) {
        float x = 0.0f;
        #pragma unroll
        for (int w = 0; w < NWARPS; w++) x += wsum[w];
        atomicAdd(&g_acc, (double)x);
        __threadfence();
        unsigned old = atomicInc(&g_count, gridDim.x - 1);
        if (old == gridDim.x - 1) {
            unsigned long long raw =
                atomicExch((unsigned long long*)&g_acc, 0ull);
            out[0] = (float)__longlong_as_double(raw);
        }
    }
}

extern "C" void kernel_launch(void* const* d_in, const int* in_sizes, int n_in,
                              void* d_out, int out_size)
{
    const float* bboxp = (const float*)d_in[0];     // (N,15,7,7)
    const float* clsp  = (const float*)d_in[1];     // (N,2)
    const float* bbox  = (const float*)d_in[2];     // (N,5,7,7)
    const int*   cls32 = (const int*)d_in[3];       // (N,) int64 -> int32 pairs

    const int N = in_sizes[3];
    int nblocks = GRID_BLOCKS;
    int total_warps = nblocks * NWARPS;
    int chunk = (N + total_warps - 1) / total_warps;      // samples per warp
    // shrink grid if N is small
    int needed = (N + chunk * NWARPS - 1) / (chunk * NWARPS);
    if (needed < nblocks) nblocks = needed;

    loss_fused_kernel<<<nblocks, 32 * NWARPS>>>(bboxp, clsp, bbox, cls32,
                                                (float*)d_out, N, chunk);
}

// round 10
// speedup vs baseline: 1.2718x; 1.2718x over previous
#include <cuda_runtime.h>

#define GDIM 7
#define GG 49
#define NWARPS 4             // one sample per warp, 128-thread blocks

__device__ double   g_acc   = 0.0;
__device__ unsigned g_count = 0u;

__device__ __forceinline__ float ldg64(const float* p) {
    float v;
    asm volatile("ld.global.L2::64B.f32 %0, [%1];" : "=f"(v) : "l"(p));
    return v;
}

__global__ void __launch_bounds__(32 * NWARPS, 16)
loss_fused_kernel(const float* __restrict__ bboxp,   // (N,15,7,7)
                  const float* __restrict__ clsp,    // (N,2)
                  const float* __restrict__ bbox,    // (N,5,7,7)
                  const int*   __restrict__ cls32,   // (N,) int64 as int32 pairs
                  float* __restrict__ out,
                  int N)
{
    const unsigned FULL = 0xffffffffu;
    const int warp = threadIdx.x >> 5;
    const int l    = threadIdx.x & 31;
    const int b    = blockIdx.x * NWARPS + warp;

    float tot = 0.0f;

    if (b < N) {
        const float* bb = bbox  + (size_t)b * (5 * GG);
        const float* bp = bboxp + (size_t)b * (15 * GG);
        const bool hi = (l < GG - 32);                  // l < 17

        // ---- independent streamed loads up front (64B fetch granularity) ----
        float p0  = ldg64(bb + l);
        float p1  = hi ? ldg64(bb + l + 32) : 0.0f;
        float q0a = ldg64(bp + l);
        float q1a = hi ? ldg64(bp + l + 32) : 0.5f;
        float q0b = ldg64(bp + 5*GG + l);
        float q1b = hi ? ldg64(bp + 5*GG + l + 32) : 0.5f;
        float q0c = ldg64(bp + 10*GG + l);
        float q1c = hi ? ldg64(bp + 10*GG + l + 32) : 0.5f;

        float c0 = 0.f, c1 = 0.f; int y = 1;
        if (l == 0) {
            c0 = ldg64(clsp + 2 * (size_t)b);
            c1 = ldg64(clsp + 2 * (size_t)b + 1);
            int yv;
            asm volatile("ld.global.L2::64B.s32 %0, [%1];"
                         : "=r"(yv) : "l"(cls32 + 2 * (size_t)b));
            y = yv;
        }

        // ---- exact argmax: REDUX on positive-float bits + ballots ----
        const unsigned w0 = __float_as_uint(p0);              // probs > 0
        const unsigned w1 = hi ? __float_as_uint(p1) : 0u;
        const unsigned vmax = __reduce_max_sync(FULL, w0 > w1 ? w0 : w1);
        const unsigned bal0 = __ballot_sync(FULL, w0 == vmax);
        const unsigned bal1 = __ballot_sync(FULL, w1 == vmax);
        const int m = bal0 ? (__ffs(bal0) - 1) : (32 + __ffs(bal1) - 1);
        const float jf  = (float)(m % GDIM);
        const float if_ = (float)(m / GDIM);

        // ---- dependent gather: exactly 16 useful cell-m values ----
        // lanes 0..11  -> bp channel 5*(l/4) + (l%4) + 1   (anchor boxes)
        // lanes 12..15 -> bb channel (l-11)                (gt box)
        float g = 0.0f;
        if (l < 16) {
            const float* gptr = (l < 12)
                ? bp + ((l >> 2) * 5 + (l & 3) + 1) * GG + m
                : bb + (l - 11) * GG + m;
            g = ldg64(gptr);
        }

        // ---- independent log work overlaps the gather latency ----
        float P = (1.0f - q0a) * (1.0f - q0b) * (1.0f - q0c);
        if (hi) P *= (1.0f - q1a) * (1.0f - q1b) * (1.0f - q1c);
        float s = -__logf(P);                      // sum of -log(1-q), this lane

        // ---- broadcast gt; lanes 0..2 own one anchor each ----
        const float gt1 = __shfl_sync(FULL, g, 12);
        const float gt2 = __shfl_sync(FULL, g, 13);
        const float gt3 = __shfl_sync(FULL, g, 14);
        const float gt4 = __shfl_sync(FULL, g, 15);

        const int al = 4 * min(l, 2);
        const float a1 = __shfl_sync(FULL, g, al + 0);
        const float a2 = __shfl_sync(FULL, g, al + 1);
        const float a3 = __shfl_sync(FULL, g, al + 2);
        const float a4 = __shfl_sync(FULL, g, al + 3);

        // ---- IoU on lanes 0..2; winner via one packed REDUX ----
        const float inv7 = 1.0f / 7.0f;
        const float tx  = (gt1 + jf)  * inv7;
        const float ty  = (gt2 + if_) * inv7;
        const float tx1 = tx - gt3 * 0.5f, tx2 = tx + gt3 * 0.5f;
        const float ty1 = ty - gt4 * 0.5f, ty2 = ty + gt4 * 0.5f;
        const float tarea = (tx2 - tx1) * (ty2 - ty1);

        const float ax  = (a1 + jf)  * inv7;
        const float ay  = (a2 + if_) * inv7;
        const float ax1 = ax - a3 * 0.5f, ax2 = ax + a3 * 0.5f;
        const float ay1 = ay - a4 * 0.5f, ay2 = ay + a4 * 0.5f;
        float iw = fmaxf(fminf(ax2, tx2) - fmaxf(ax1, tx1), 0.0f);
        float ih = fmaxf(fminf(ay2, ty2) - fmaxf(ay1, ty1), 0.0f);
        float inter = iw * ih;
        float uni   = (ax2 - ax1) * (ay2 - ay1) + tarea - inter;
        float iou   = __fdividef(inter, uni + 1e-9f);

        // max of (iou bits | (3 - anchor)) -> best iou, first index on ties
        unsigned key = (l < 3) ? ((__float_as_uint(iou) & ~3u) | (3u - l)) : 0u;
        key = __reduce_max_sync(FULL, key);
        const int best = 3 - (int)(key & 3u);

        // ---- BCE correction for best anchor: -p * (log q - log(1-q)) ----
        float qb0 = (best == 0) ? q0a : (best == 1) ? q0b : q0c;
        s -= p0 * (__logf(qb0) - __logf(1.0f - qb0));
        if (hi) {
            float qb1 = (best == 0) ? q1a : (best == 1) ? q1b : q1c;
            s -= p1 * (__logf(qb1) - __logf(1.0f - qb1));
        }

        tot = s * (1.0f / ((float)N * 49.0f));

        // ---- coord + size computed on the winning anchor's lane ----
        if (l == best) {
            float coord = -(gt1 * __logf(a1) + (1.0f - gt1) * __logf(1.0f - a1))
                        + -(gt2 * __logf(a2) + (1.0f - gt2) * __logf(1.0f - a2));
            float size_ = fabsf(__logf(a3) - __logf(gt3))
                        + fabsf(__logf(a4) - __logf(gt4));
            tot += coord + size_;
        }

        // ---- CE on lane 0 ----
        if (l == 0) {
            float mx  = fmaxf(c0, c1);
            float lse = mx + __logf(__expf(c0 - mx) + __expf(c1 - mx));
            float sel = (y == 1) ? c0 : c1;
            tot += (lse - sel) * (1.0f / (float)N);
        }
    }

    // ---- warp reduce ----
    #pragma unroll
    for (int off = 16; off; off >>= 1)
        tot += __shfl_xor_sync(FULL, tot, off);

    // ---- block reduce -> one double atomic per block ----
    __shared__ float wsum[NWARPS];
    if (l == 0) wsum[warp] = tot;
    __syncthreads();
    if (threadIdx.x == 0) {
        float x = 0.0f;
        #pragma unroll
        for (int w = 0; w < NWARPS; w++) x += wsum[w];
        atomicAdd(&g_acc, (double)x);
        __threadfence();
        unsigned old = atomicInc(&g_count, gridDim.x - 1);
        if (old == gridDim.x - 1) {
            unsigned long long raw =
                atomicExch((unsigned long long*)&g_acc, 0ull);
            out[0] = (float)__longlong_as_double(raw);
        }
    }
}

extern "C" void kernel_launch(void* const* d_in, const int* in_sizes, int n_in,
                              void* d_out, int out_size)
{
    const float* bboxp = (const float*)d_in[0];     // (N,15,7,7)
    const float* clsp  = (const float*)d_in[1];     // (N,2)
    const float* bbox  = (const float*)d_in[2];     // (N,5,7,7)
    const int*   cls32 = (const int*)d_in[3];       // (N,) int64 -> int32 pairs

    const int N = in_sizes[3];
    const int nblocks = (N + NWARPS - 1) / NWARPS;

    loss_fused_kernel<<<nblocks, 32 * NWARPS>>>(bboxp, clsp, bbox, cls32,
                                                (float*)d_out, N);
}